// round 7
// baseline (speedup 1.0000x reference)
#include <cuda_runtime.h>
#include <cuda_bf16.h>

#define FULLMASK 0xffffffffu

__device__ __forceinline__ void stcs4(float* p, float4 v) {
    asm volatile("st.global.cs.v4.f32 [%0], {%1,%2,%3,%4};"
                 :: "l"(p), "f"(v.x), "f"(v.y), "f"(v.z), "f"(v.w) : "memory");
}

// Register-rolling separable 4x4 depthwise blur.
// Full-width warp rows: each warp owns all 256 cols of its row strip.
// lane L owns cols [4L..4L+3] (a) and [128+4L..131+4L] (b). All horizontal
// halos come from warp shuffles or the zero image boundary -> zero edge loads.
// out[y,x] = sum_{a,b} k[a][b] * in[y+1-a, x+1-b]   (zero pad outside)
__global__ __launch_bounds__(256, 5)
void Blur2_kernel(const float* __restrict__ in,
                  const float* __restrict__ kern,
                  float* __restrict__ out) {
    const int lane = threadIdx.x & 31;
    const int warp = threadIdx.x >> 5;            // 0..7 -> 16-row strip
    const int x0   = lane << 2;
    const int z    = blockIdx.y;                  // n*c fold (1024)
    const int y0   = (blockIdx.x << 7) + (warp << 4);

    const float* __restrict__ base  = in  + (size_t)z * 65536;
    float*       __restrict__ obase = out + (size_t)z * 65536;

    // separable factors (rank-1 kernel): h(c)=w3*x(c-2)+w2*x(c-1)+w1*x(c)+w0*x(c+1)
    const float w0 = kern[0], w1 = kern[1], w2 = kern[2], w3 = kern[3];
    const float rk = 1.0f / w0;
    const float u1 = kern[4] * rk, u2 = kern[8] * rk, u3 = kern[12] * rk;

    auto ldrow = [&](int gy, float4& a, float4& b) {
        a = make_float4(0.f, 0.f, 0.f, 0.f);
        b = a;
        if ((unsigned)gy < 256u) {
            const float* rp = base + (gy << 8) + x0;
            a = *(const float4*)rp;
            b = *(const float4*)(rp + 128);
        }
    };

    auto hcalc = [&](const float4& a, const float4& b, float4& hA, float4& hB) {
        float am2 = __shfl_up_sync(FULLMASK, a.z, 1);     // col 4L-2
        float am1 = __shfl_up_sync(FULLMASK, a.w, 1);     // col 4L-1
        float ap4 = __shfl_down_sync(FULLMASK, a.x, 1);   // col 4L+4
        float bm2 = __shfl_up_sync(FULLMASK, b.z, 1);     // col 126+4L
        float bm1 = __shfl_up_sync(FULLMASK, b.w, 1);     // col 127+4L
        float bp4 = __shfl_down_sync(FULLMASK, b.x, 1);   // col 132+4L
        const float b0x  = __shfl_sync(FULLMASK, b.x, 0);   // col 128
        const float a31z = __shfl_sync(FULLMASK, a.z, 31);  // col 126
        const float a31w = __shfl_sync(FULLMASK, a.w, 31);  // col 127
        if (lane == 0)  { am2 = 0.f; am1 = 0.f; bm2 = a31z; bm1 = a31w; }
        if (lane == 31) { ap4 = b0x; bp4 = 0.f; }
        hA.x = fmaf(w3, am2, fmaf(w2, am1, fmaf(w1, a.x, w0 * a.y)));
        hA.y = fmaf(w3, am1, fmaf(w2, a.x, fmaf(w1, a.y, w0 * a.z)));
        hA.z = fmaf(w3, a.x, fmaf(w2, a.y, fmaf(w1, a.z, w0 * a.w)));
        hA.w = fmaf(w3, a.y, fmaf(w2, a.z, fmaf(w1, a.w, w0 * ap4)));
        hB.x = fmaf(w3, bm2, fmaf(w2, bm1, fmaf(w1, b.x, w0 * b.y)));
        hB.y = fmaf(w3, bm1, fmaf(w2, b.x, fmaf(w1, b.y, w0 * b.z)));
        hB.z = fmaf(w3, b.x, fmaf(w2, b.y, fmaf(w1, b.z, w0 * b.w)));
        hB.w = fmaf(w3, b.y, fmaf(w2, b.z, fmaf(w1, b.w, w0 * bp4)));
    };

    // prologue: h for rows y0-2, y0-1, y0 (loads batched)
    float4 hA0, hB0, hA1, hB1, hA2, hB2;
    {
        float4 a0, b0, a1, b1, a2, b2;
        ldrow(y0 - 2, a0, b0);
        ldrow(y0 - 1, a1, b1);
        ldrow(y0,     a2, b2);
        hcalc(a0, b0, hA0, hB0);
        hcalc(a1, b1, hA1, hB1);
        hcalc(a2, b2, hA2, hB2);
    }

    #pragma unroll
    for (int i = 0; i < 16; i += 2) {
        float4 a1, b1, a2, b2;
        ldrow(y0 + 1 + i, a1, b1);     // 4 independent LDG.128 batched
        ldrow(y0 + 2 + i, a2, b2);

        float* op = obase + ((y0 + i) << 8) + x0;

        float4 h3A, h3B;
        hcalc(a1, b1, h3A, h3B);
        float4 o;
        o.x = fmaf(u3, hA0.x, fmaf(u2, hA1.x, fmaf(u1, hA2.x, h3A.x)));
        o.y = fmaf(u3, hA0.y, fmaf(u2, hA1.y, fmaf(u1, hA2.y, h3A.y)));
        o.z = fmaf(u3, hA0.z, fmaf(u2, hA1.z, fmaf(u1, hA2.z, h3A.z)));
        o.w = fmaf(u3, hA0.w, fmaf(u2, hA1.w, fmaf(u1, hA2.w, h3A.w)));
        stcs4(op, o);
        o.x = fmaf(u3, hB0.x, fmaf(u2, hB1.x, fmaf(u1, hB2.x, h3B.x)));
        o.y = fmaf(u3, hB0.y, fmaf(u2, hB1.y, fmaf(u1, hB2.y, h3B.y)));
        o.z = fmaf(u3, hB0.z, fmaf(u2, hB1.z, fmaf(u1, hB2.z, h3B.z)));
        o.w = fmaf(u3, hB0.w, fmaf(u2, hB1.w, fmaf(u1, hB2.w, h3B.w)));
        stcs4(op + 128, o);

        float4 h4A, h4B;
        hcalc(a2, b2, h4A, h4B);
        o.x = fmaf(u3, hA1.x, fmaf(u2, hA2.x, fmaf(u1, h3A.x, h4A.x)));
        o.y = fmaf(u3, hA1.y, fmaf(u2, hA2.y, fmaf(u1, h3A.y, h4A.y)));
        o.z = fmaf(u3, hA1.z, fmaf(u2, hA2.z, fmaf(u1, h3A.z, h4A.z)));
        o.w = fmaf(u3, hA1.w, fmaf(u2, hA2.w, fmaf(u1, h3A.w, h4A.w)));
        stcs4(op + 256, o);
        o.x = fmaf(u3, hB1.x, fmaf(u2, hB2.x, fmaf(u1, h3B.x, h4B.x)));
        o.y = fmaf(u3, hB1.y, fmaf(u2, hB2.y, fmaf(u1, h3B.y, h4B.y)));
        o.z = fmaf(u3, hB1.z, fmaf(u2, hB2.z, fmaf(u1, h3B.z, h4B.z)));
        o.w = fmaf(u3, hB1.w, fmaf(u2, hB2.w, fmaf(u1, h3B.w, h4B.w)));
        stcs4(op + 384, o);

        hA0 = hA2; hA1 = h3A; hA2 = h4A;
        hB0 = hB2; hB1 = h3B; hB2 = h4B;
    }
}

extern "C" void kernel_launch(void* const* d_in, const int* in_sizes, int n_in,
                              void* d_out, int out_size) {
    int xi = 0, ki = 1;
    if (n_in >= 2 && in_sizes[0] == 16) { xi = 1; ki = 0; }
    const float* x = (const float*)d_in[xi];
    const float* k = (const float*)d_in[ki];
    float* o       = (float*)d_out;

    const int nc = in_sizes[xi] / 65536;   // 1024
    dim3 grid(2, nc);                      // CTA covers 128 rows x 256 cols
    dim3 block(256);
    Blur2_kernel<<<grid, block>>>(x, k, o);
}

// round 9
// speedup vs baseline: 1.1160x; 1.1160x over previous
#include <cuda_runtime.h>
#include <cuda_bf16.h>
#include <cstdint>

#define FULLMASK 0xffffffffu
#define CP_WAIT(N) asm volatile("cp.async.wait_group %0;" :: "n"(N) : "memory")

__device__ __forceinline__ void stcs4(float* p, float4 v) {
    asm volatile("st.global.cs.v4.f32 [%0], {%1,%2,%3,%4};"
                 :: "l"(p), "f"(v.x), "f"(v.y), "f"(v.z), "f"(v.w) : "memory");
}

// Separable 4x4 depthwise blur, cp.async-pipelined per-warp SMEM row ring.
// Warp owns all 256 cols of a 16-row strip; lane L holds cols [4L..4L+3] (a)
// and [128+4L..131+4L] (b). Horizontal halos via warp shuffle / zero boundary.
// Ring of 8 input rows per warp in SMEM; steady state keeps 4 rows in flight.
// out[y,x] = sum_{a,b} k[a][b] * in[y+1-a, x+1-b]   (zero pad outside)
__global__ __launch_bounds__(128)
void Blur2_kernel(const float* __restrict__ in,
                  const float* __restrict__ kern,
                  float* __restrict__ out) {
    __shared__ __align__(16) float ring[4][8][256];   // [warp][slot][col] = 32KB

    const int lane = threadIdx.x & 31;
    const int warp = threadIdx.x >> 5;               // 0..3
    const int x0   = lane << 2;
    const int z    = blockIdx.y;                     // n*c fold
    const int y0   = (blockIdx.x << 6) + (warp << 4);

    const float* __restrict__ base  = in  + (size_t)z * 65536;
    float*       __restrict__ obase = out + (size_t)z * 65536;

    const float w0 = kern[0], w1 = kern[1], w2 = kern[2], w3 = kern[3];
    const float rk = 1.0f / w0;
    const float u1 = kern[4] * rk, u2 = kern[8] * rk, u3 = kern[12] * rk;

    float* my0 = &ring[warp][0][x0];           // slot stride = 256 floats
    float* my1 = &ring[warp][0][x0 + 128];
    const unsigned int s0 = (unsigned int)__cvta_generic_to_shared(my0);

    // issue one input row (2x16B cp.async) into ring slot; always commits a group
    auto issue_row = [&](int gy, int slot) {
        if ((unsigned)gy < 256u) {
            const float* rp = base + (gy << 8) + x0;
            const unsigned int d0 = s0 + slot * 1024;
            asm volatile("cp.async.cg.shared.global [%0], [%1], 16;"
                         :: "r"(d0), "l"(rp) : "memory");
            asm volatile("cp.async.cg.shared.global [%0], [%1], 16;"
                         :: "r"(d0 + 512), "l"(rp + 128) : "memory");
        } else {
            const float4 zz = make_float4(0.f, 0.f, 0.f, 0.f);
            *(float4*)(my0 + slot * 256) = zz;
            *(float4*)(my1 + slot * 256) = zz;
        }
        asm volatile("cp.async.commit_group;" ::: "memory");
    };

    auto hcalc = [&](const float4& a, const float4& b, float4& hA, float4& hB) {
        float am2 = __shfl_up_sync(FULLMASK, a.z, 1);
        float am1 = __shfl_up_sync(FULLMASK, a.w, 1);
        float ap4 = __shfl_down_sync(FULLMASK, a.x, 1);
        float bm2 = __shfl_up_sync(FULLMASK, b.z, 1);
        float bm1 = __shfl_up_sync(FULLMASK, b.w, 1);
        float bp4 = __shfl_down_sync(FULLMASK, b.x, 1);
        const float b0x  = __shfl_sync(FULLMASK, b.x, 0);
        const float a31z = __shfl_sync(FULLMASK, a.z, 31);
        const float a31w = __shfl_sync(FULLMASK, a.w, 31);
        if (lane == 0)  { am2 = 0.f; am1 = 0.f; bm2 = a31z; bm1 = a31w; }
        if (lane == 31) { ap4 = b0x; bp4 = 0.f; }
        hA.x = fmaf(w3, am2, fmaf(w2, am1, fmaf(w1, a.x, w0 * a.y)));
        hA.y = fmaf(w3, am1, fmaf(w2, a.x, fmaf(w1, a.y, w0 * a.z)));
        hA.z = fmaf(w3, a.x, fmaf(w2, a.y, fmaf(w1, a.z, w0 * a.w)));
        hA.w = fmaf(w3, a.y, fmaf(w2, a.z, fmaf(w1, a.w, w0 * ap4)));
        hB.x = fmaf(w3, bm2, fmaf(w2, bm1, fmaf(w1, b.x, w0 * b.y)));
        hB.y = fmaf(w3, bm1, fmaf(w2, b.x, fmaf(w1, b.y, w0 * b.z)));
        hB.z = fmaf(w3, b.x, fmaf(w2, b.y, fmaf(w1, b.z, w0 * b.w)));
        hB.w = fmaf(w3, b.y, fmaf(w2, b.z, fmaf(w1, b.w, w0 * bp4)));
    };

    // prologue: fill all 8 ring slots (rows y0-2 .. y0+5), one group per row
    #pragma unroll
    for (int j = 0; j < 8; j++) issue_row(y0 - 2 + j, j);

    float4 hA0, hB0, hA1, hB1, hA2, hB2;
    CP_WAIT(5);   // first 3 rows arrived
    {
        float4 a, b;
        a = *(const float4*)(my0);       b = *(const float4*)(my1);
        hcalc(a, b, hA0, hB0);
        a = *(const float4*)(my0 + 256); b = *(const float4*)(my1 + 256);
        hcalc(a, b, hA1, hB1);
        a = *(const float4*)(my0 + 512); b = *(const float4*)(my1 + 512);
        hcalc(a, b, hA2, hB2);
    }

    // one output row: consume ring slot (i+3)&7, combine with h-ring, store
    auto body = [&](int i) {
        const int s = (i + 3) & 7;
        const float4 a = *(const float4*)(my0 + s * 256);
        const float4 b = *(const float4*)(my1 + s * 256);
        float4 h3A, h3B;
        hcalc(a, b, h3A, h3B);
        float* op = obase + ((y0 + i) << 8) + x0;
        float4 o;
        o.x = fmaf(u3, hA0.x, fmaf(u2, hA1.x, fmaf(u1, hA2.x, h3A.x)));
        o.y = fmaf(u3, hA0.y, fmaf(u2, hA1.y, fmaf(u1, hA2.y, h3A.y)));
        o.z = fmaf(u3, hA0.z, fmaf(u2, hA1.z, fmaf(u1, hA2.z, h3A.z)));
        o.w = fmaf(u3, hA0.w, fmaf(u2, hA1.w, fmaf(u1, hA2.w, h3A.w)));
        stcs4(op, o);
        o.x = fmaf(u3, hB0.x, fmaf(u2, hB1.x, fmaf(u1, hB2.x, h3B.x)));
        o.y = fmaf(u3, hB0.y, fmaf(u2, hB1.y, fmaf(u1, hB2.y, h3B.y)));
        o.z = fmaf(u3, hB0.z, fmaf(u2, hB1.z, fmaf(u1, hB2.z, h3B.z)));
        o.w = fmaf(u3, hB0.w, fmaf(u2, hB1.w, fmaf(u1, hB2.w, h3B.w)));
        stcs4(op + 128, o);
        hA0 = hA1; hA1 = hA2; hA2 = h3A;
        hB0 = hB1; hB1 = hB2; hB2 = h3B;
    };

    // steady state: wait (all but last 4 groups), consume, prefetch next row
    #pragma unroll
    for (int i = 0; i < 11; i++) {
        CP_WAIT(4);
        body(i);
        issue_row(y0 + 6 + i, i & 7);    // rows y0+6 .. y0+16
    }
    // drain tail (no more prefetches; 19 groups total issued)
    CP_WAIT(4); body(11);
    CP_WAIT(3); body(12);
    CP_WAIT(2); body(13);
    CP_WAIT(1); body(14);
    CP_WAIT(0); body(15);
}

extern "C" void kernel_launch(void* const* d_in, const int* in_sizes, int n_in,
                              void* d_out, int out_size) {
    int xi = 0, ki = 1;
    if (n_in >= 2 && in_sizes[0] == 16) { xi = 1; ki = 0; }
    const float* x = (const float*)d_in[xi];
    const float* k = (const float*)d_in[ki];
    float* o       = (float*)d_out;

    const int nc = in_sizes[xi] / 65536;   // 1024
    dim3 grid(4, nc);                      // CTA covers 64 rows x 256 cols
    dim3 block(128);
    Blur2_kernel<<<grid, block>>>(x, k, o);
}

// round 10
// speedup vs baseline: 1.1285x; 1.0112x over previous
#include <cuda_runtime.h>
#include <cuda_bf16.h>
#include <cstdint>

#define IMG_H 256
#define IMG_W 256
#define FULLMASK 0xffffffffu

struct Row { float4 m; float lx, ly, r; };

__device__ __forceinline__ void stcs4(float* p, float4 v) {
    asm volatile("st.global.cs.v4.f32 [%0], {%1,%2,%3,%4};"
                 :: "l"(p), "f"(v.x), "f"(v.y), "f"(v.z), "f"(v.w) : "memory");
}

__device__ __forceinline__ float4 ldg256(const float* p) {
    float4 v;
    asm volatile("ld.global.nc.L2::256B.v4.f32 {%0,%1,%2,%3}, [%4];"
                 : "=f"(v.x), "=f"(v.y), "=f"(v.z), "=f"(v.w) : "l"(p));
    return v;
}

// Register-rolling separable 4x4 depthwise blur.
// Warp-shuffle halo, 4-row load batching, streaming stores, 128-thread CTAs
// (8 CTAs/SM at 60 regs -> 32 warps), L2::256B read promotion.
// out[y,x] = sum_{a,b} k[a][b] * in[y+1-a, x+1-b]   (zero pad outside)
__global__ __launch_bounds__(128)
void Blur2_kernel(const float* __restrict__ in,
                  const float* __restrict__ kern,
                  float* __restrict__ out) {
    const int t     = threadIdx.x;
    const int lane  = t & 31;
    const int warp  = t >> 5;           // 0..3
    const int seg   = warp & 1;         // column segment: 0 or 1
    const int strip = warp >> 1;        // 0..1
    const int xg    = seg * 128 + lane * 4;
    const int z     = blockIdx.y;       // n*c fold (1024)
    const int y0    = blockIdx.x * 32 + strip * 16;

    const float* __restrict__ base  = in  + (size_t)z * (IMG_H * IMG_W);
    float*       __restrict__ obase = out + (size_t)z * (IMG_H * IMG_W);

    // separable factors (rank-1 kernel)
    const float w0 = kern[0], w1 = kern[1], w2 = kern[2], w3 = kern[3];
    const float rk = 1.0f / w0;
    const float u1 = kern[4] * rk, u2 = kern[8] * rk, u3 = kern[12] * rk;

    const bool left_edge_load  = (lane == 0)  && (seg == 1);
    const bool right_edge_load = (lane == 31) && (seg == 0);

    auto loadrow = [&](int gy) -> Row {
        Row v;
        v.m = make_float4(0.f, 0.f, 0.f, 0.f);
        v.lx = 0.f; v.ly = 0.f; v.r = 0.f;
        if ((unsigned)gy < (unsigned)IMG_H) {
            const float* rp = base + gy * IMG_W + xg;
            v.m = ldg256(rp);
            if (left_edge_load)  { const float2 e = *(const float2*)(rp - 2); v.lx = e.x; v.ly = e.y; }
            if (right_edge_load) { v.r = rp[4]; }
        }
        return v;
    };

    auto hcalc = [&](const Row& v) -> float4 {
        float cm2 = __shfl_up_sync(FULLMASK, v.m.z, 1);
        float cm1 = __shfl_up_sync(FULLMASK, v.m.w, 1);
        float p4  = __shfl_down_sync(FULLMASK, v.m.x, 1);
        if (lane == 0)  { cm2 = v.lx; cm1 = v.ly; }
        if (lane == 31) { p4 = v.r; }
        float4 h;
        h.x = fmaf(w3, cm2,   fmaf(w2, cm1,   fmaf(w1, v.m.x, w0 * v.m.y)));
        h.y = fmaf(w3, cm1,   fmaf(w2, v.m.x, fmaf(w1, v.m.y, w0 * v.m.z)));
        h.z = fmaf(w3, v.m.x, fmaf(w2, v.m.y, fmaf(w1, v.m.z, w0 * v.m.w)));
        h.w = fmaf(w3, v.m.y, fmaf(w2, v.m.z, fmaf(w1, v.m.w, w0 * p4)));
        return h;
    };

    // prologue: rows y0-2, y0-1, y0
    Row p0 = loadrow(y0 - 2);
    Row p1 = loadrow(y0 - 1);
    Row p2 = loadrow(y0);
    float4 h0 = hcalc(p0);
    float4 h1 = hcalc(p1);
    float4 h2 = hcalc(p2);

    #pragma unroll
    for (int i = 0; i < 16; i += 4) {
        // batch independent LDGs for the next 4 rows
        Row a = loadrow(y0 + 1 + i);
        Row b = loadrow(y0 + 2 + i);
        Row c = loadrow(y0 + 3 + i);
        Row d = loadrow(y0 + 4 + i);

        float* op = obase + (y0 + i) * IMG_W + xg;

        float4 h3 = hcalc(a);
        float4 o;
        o.x = fmaf(u3, h0.x, fmaf(u2, h1.x, fmaf(u1, h2.x, h3.x)));
        o.y = fmaf(u3, h0.y, fmaf(u2, h1.y, fmaf(u1, h2.y, h3.y)));
        o.z = fmaf(u3, h0.z, fmaf(u2, h1.z, fmaf(u1, h2.z, h3.z)));
        o.w = fmaf(u3, h0.w, fmaf(u2, h1.w, fmaf(u1, h2.w, h3.w)));
        stcs4(op, o);

        float4 h4 = hcalc(b);
        o.x = fmaf(u3, h1.x, fmaf(u2, h2.x, fmaf(u1, h3.x, h4.x)));
        o.y = fmaf(u3, h1.y, fmaf(u2, h2.y, fmaf(u1, h3.y, h4.y)));
        o.z = fmaf(u3, h1.z, fmaf(u2, h2.z, fmaf(u1, h3.z, h4.z)));
        o.w = fmaf(u3, h1.w, fmaf(u2, h2.w, fmaf(u1, h3.w, h4.w)));
        stcs4(op + IMG_W, o);

        float4 h5 = hcalc(c);
        o.x = fmaf(u3, h2.x, fmaf(u2, h3.x, fmaf(u1, h4.x, h5.x)));
        o.y = fmaf(u3, h2.y, fmaf(u2, h3.y, fmaf(u1, h4.y, h5.y)));
        o.z = fmaf(u3, h2.z, fmaf(u2, h3.z, fmaf(u1, h4.z, h5.z)));
        o.w = fmaf(u3, h2.w, fmaf(u2, h3.w, fmaf(u1, h4.w, h5.w)));
        stcs4(op + 2 * IMG_W, o);

        float4 h6 = hcalc(d);
        o.x = fmaf(u3, h3.x, fmaf(u2, h4.x, fmaf(u1, h5.x, h6.x)));
        o.y = fmaf(u3, h3.y, fmaf(u2, h4.y, fmaf(u1, h5.y, h6.y)));
        o.z = fmaf(u3, h3.z, fmaf(u2, h4.z, fmaf(u1, h5.z, h6.z)));
        o.w = fmaf(u3, h3.w, fmaf(u2, h4.w, fmaf(u1, h5.w, h6.w)));
        stcs4(op + 3 * IMG_W, o);

        h0 = h4; h1 = h5; h2 = h6;
    }
}

extern "C" void kernel_launch(void* const* d_in, const int* in_sizes, int n_in,
                              void* d_out, int out_size) {
    int xi = 0, ki = 1;
    if (n_in >= 2 && in_sizes[0] == 16) { xi = 1; ki = 0; }
    const float* x = (const float*)d_in[xi];
    const float* k = (const float*)d_in[ki];
    float* o       = (float*)d_out;

    const int nc = in_sizes[xi] / (IMG_H * IMG_W);   // 1024
    dim3 grid(IMG_H / 32, nc);                        // (8, 1024)
    dim3 block(128);
    Blur2_kernel<<<grid, block>>>(x, k, o);
}